// round 14
// baseline (speedup 1.0000x reference)
#include <cuda_runtime.h>
#include <cuda_bf16.h>
#include <cstdint>
#include <math.h>

#define NTOK 4096
#define DDIM 768
#define HDIM 1536
#define NE   6

// ---------------- device scratch ----------------
__device__ int   g_perm[NTOK];
__device__ int   g_gstart[NE + 1];
__device__ float g_alpha[NE];
__device__ int   g_c1[NE * 64];                              // GEMM1 tile-completion per (g,mx)
__device__ int   g_c2[NE * 64];                              // GEMM2 tile-completion per (g,mx)
__device__ __nv_bfloat16 g_xg[(size_t)NTOK * DDIM];          // gathered x, perm order (bf16)
__device__ __nv_bfloat16 g_h [(size_t)NTOK * HDIM];          // relu hidden, perm order
__device__ __nv_bfloat16 g_W1b[(size_t)NE * DDIM * HDIM];    // bf16 W1, native [e][d][h]
__device__ __nv_bfloat16 g_W2b[(size_t)NE * HDIM * DDIM];    // bf16 W2, native [e][h][d]
__device__ float g_pre[(size_t)NTOK * DDIM];                 // x + alpha*r, token order

// ---------------- asm helpers ----------------
__device__ __forceinline__ void cp_async16(void* smem, const void* g, bool pred) {
    uint32_t s = (uint32_t)__cvta_generic_to_shared(smem);
    int sz = pred ? 16 : 0;   // src-size 0 -> 16B zero-fill
    asm volatile("cp.async.cg.shared.global [%0], [%1], 16, %2;\n" :: "r"(s), "l"(g), "r"(sz));
}
#define CP_COMMIT() asm volatile("cp.async.commit_group;\n" ::: "memory")
#define CP_WAIT1()  asm volatile("cp.async.wait_group 1;\n" ::: "memory")

__device__ __forceinline__ void ldsm_x4(uint32_t& r0, uint32_t& r1, uint32_t& r2, uint32_t& r3,
                                        uint32_t addr) {
    asm volatile("ldmatrix.sync.aligned.m8n8.x4.shared.b16 {%0,%1,%2,%3}, [%4];"
                 : "=r"(r0), "=r"(r1), "=r"(r2), "=r"(r3) : "r"(addr));
}
__device__ __forceinline__ void ldsm_x4_t(uint32_t& r0, uint32_t& r1, uint32_t& r2, uint32_t& r3,
                                          uint32_t addr) {
    asm volatile("ldmatrix.sync.aligned.m8n8.x4.trans.shared.b16 {%0,%1,%2,%3}, [%4];"
                 : "=r"(r0), "=r"(r1), "=r"(r2), "=r"(r3) : "r"(addr));
}

__device__ __forceinline__ void mma16816(float* c, const uint32_t* a, const uint32_t* b) {
    asm volatile(
        "mma.sync.aligned.m16n8k16.row.col.f32.bf16.bf16.f32 "
        "{%0,%1,%2,%3}, {%4,%5,%6,%7}, {%8,%9}, {%0,%1,%2,%3};\n"
        : "+f"(c[0]), "+f"(c[1]), "+f"(c[2]), "+f"(c[3])
        : "r"(a[0]), "r"(a[1]), "r"(a[2]), "r"(a[3]), "r"(b[0]), "r"(b[1]));
}

// ---------------- prep: sort tokens by group + zero counters ----------------
__global__ void prep_kernel(const int* __restrict__ ids,
                            const int* __restrict__ e2g,
                            const float* __restrict__ raw_alpha,
                            int T) {
    __shared__ int cnt[NE];
    __shared__ int cur[NE];
    __shared__ unsigned char gid_s[NTOK];
    int tid = threadIdx.x;
    if (tid < NE) cnt[tid] = 0;
    for (int i = tid; i < NE * 64; i += blockDim.x) { g_c1[i] = 0; g_c2[i] = 0; }
    __syncthreads();
    for (int i = tid; i < NTOK; i += blockDim.x) {
        int ty = ids[i];
        ty = ty < 0 ? 0 : (ty > T - 1 ? T - 1 : ty);
        int gd = e2g[ty];
        gid_s[i] = (unsigned char)gd;
        atomicAdd(&cnt[gd], 1);
    }
    __syncthreads();
    if (tid == 0) {
        int acc = 0;
        for (int e = 0; e < NE; e++) { g_gstart[e] = acc; cur[e] = acc; acc += cnt[e]; }
        g_gstart[NE] = acc;
    }
    __syncthreads();
    for (int i = tid; i < NTOK; i += blockDim.x) {
        int pos = atomicAdd(&cur[gid_s[i]], 1);
        g_perm[pos] = i;
    }
    if (tid < NE) g_alpha[tid] = 0.05f / (1.0f + expf(-raw_alpha[tid]));
}

// ---------------- streaming fp32 -> bf16 weight convert ----------------
__global__ void convert_kernel(const float* __restrict__ in, int which) {
    __nv_bfloat16* out = which ? g_W2b : g_W1b;
    size_t i0 = ((size_t)blockIdx.x * 256 + threadIdx.x) * 16;
    #pragma unroll
    for (int h = 0; h < 2; h++) {
        float4 a = *reinterpret_cast<const float4*>(in + i0 + h * 8);
        float4 b = *reinterpret_cast<const float4*>(in + i0 + h * 8 + 4);
        __nv_bfloat162 h0 = __floats2bfloat162_rn(a.x, a.y);
        __nv_bfloat162 h1 = __floats2bfloat162_rn(a.z, a.w);
        __nv_bfloat162 h2 = __floats2bfloat162_rn(b.x, b.y);
        __nv_bfloat162 h3 = __floats2bfloat162_rn(b.z, b.w);
        uint4 o;
        o.x = *reinterpret_cast<uint32_t*>(&h0);
        o.y = *reinterpret_cast<uint32_t*>(&h1);
        o.z = *reinterpret_cast<uint32_t*>(&h2);
        o.w = *reinterpret_cast<uint32_t*>(&h3);
        *reinterpret_cast<uint4*>(out + i0 + h * 8) = o;
    }
}

// ---------------- gather: one float4 per thread ----------------
__global__ void gather_kernel(const float* __restrict__ x) {
    int idx = blockIdx.x * 256 + threadIdx.x;
    int p = idx / 192, j = idx % 192;
    int t = g_perm[p];
    float4 v = *(reinterpret_cast<const float4*>(x + (size_t)t * DDIM) + j);
    __nv_bfloat162 h0 = __floats2bfloat162_rn(v.x, v.y);
    __nv_bfloat162 h1 = __floats2bfloat162_rn(v.z, v.w);
    uint2 o;
    o.x = *reinterpret_cast<uint32_t*>(&h0);
    o.y = *reinterpret_cast<uint32_t*>(&h1);
    *(reinterpret_cast<uint2*>(g_xg + (size_t)p * DDIM) + j) = o;
}

// ---------------- GEMM tile body (BM=64, BN=128, BK=32, 3-stage cp.async) ----------------
template<int K, bool EPI2>
__device__ __forceinline__ void gemm_tile(
    unsigned char* smem_raw, uint32_t sbase,
    int m0, int n0, int g, int start, int cnt,
    const float* __restrict__ bias, const float* __restrict__ x)
{
    constexpr int BM = 64, BN = 128, BK = 32;
    constexpr int LDA = 40;
    constexpr int LDB = 136;
    constexpr int NTOT = EPI2 ? DDIM : HDIM;
    constexpr int NIT  = K / BK;
    constexpr int A_ELEMS = BM * LDA;                 // 2560
    constexpr int STAGE_ELEMS = A_ELEMS + BK * LDB;   // 6912
    constexpr int STAGE_BYTES = STAGE_ELEMS * 2;      // 13824
    constexpr int B_BYTE_OFF  = A_ELEMS * 2;          // 5120

    __nv_bfloat16* smem = reinterpret_cast<__nv_bfloat16*>(smem_raw);
    const __nv_bfloat16* A  = EPI2 ? g_h   : g_xg;
    const __nv_bfloat16* Bw = EPI2 ? g_W2b : g_W1b;
    const __nv_bfloat16* Bg = Bw + (size_t)g * K * NTOT;
    const __nv_bfloat16* Ag = A + (size_t)start * K;

    int tid  = threadIdx.x;
    int warp = tid >> 5, lane = tid & 31;
    int wm = (warp & 1) * 32;
    int wn = (warp >> 1) * 32;
    int lrow = lane >> 2;
    int lcol = (lane & 3) * 2;

    int l15 = lane & 15, lhi = lane >> 4;
    uint32_t aOff[2];
    #pragma unroll
    for (int mi = 0; mi < 2; mi++)
        aOff[mi] = (uint32_t)(((wm + mi * 16 + l15) * LDA + lhi * 8) * 2);
    uint32_t bOff[2];
    #pragma unroll
    for (int j = 0; j < 2; j++)
        bOff[j] = (uint32_t)(B_BYTE_OFF + (l15 * LDB + wn + j * 16 + lhi * 8) * 2);

    auto load_stage = [&](int s, int k0) {
        __nv_bfloat16* As = smem + s * STAGE_ELEMS;
        __nv_bfloat16* Bs = As + A_ELEMS;
        {
            int r = tid >> 2, v = tid & 3;
            bool p = (m0 + r) < cnt;
            int rr = p ? (m0 + r) : 0;
            cp_async16(&As[r * LDA + v * 8], Ag + (size_t)rr * K + k0 + v * 8, p);
        }
        #pragma unroll
        for (int i = 0; i < 2; i++) {
            int c = tid + i * 256;
            int r = c >> 4, v = c & 15;
            cp_async16(&Bs[r * LDB + v * 8],
                       Bg + (size_t)(k0 + r) * NTOT + n0 + v * 8, true);
        }
    };

    float acc[2][4][4];
    #pragma unroll
    for (int mi = 0; mi < 2; mi++)
        #pragma unroll
        for (int ni = 0; ni < 4; ni++)
            #pragma unroll
            for (int qq = 0; qq < 4; qq++) acc[mi][ni][qq] = 0.f;

    // all warps done with previous work-item's smem before refilling
    __syncthreads();

    load_stage(0, 0);
    CP_COMMIT();
    load_stage(1, BK);
    CP_COMMIT();

    for (int it = 0; it < NIT; it++) {
        CP_WAIT1();
        __syncthreads();

        if (it + 2 < NIT) load_stage((it + 2) % 3, (it + 2) * BK);
        CP_COMMIT();

        uint32_t stg = sbase + (uint32_t)((it % 3) * STAGE_BYTES);
        #pragma unroll
        for (int kk = 0; kk < BK; kk += 16) {
            uint32_t af[2][4], bq[2][4];
            #pragma unroll
            for (int mi = 0; mi < 2; mi++)
                ldsm_x4(af[mi][0], af[mi][1], af[mi][2], af[mi][3],
                        stg + aOff[mi] + kk * 2);
            #pragma unroll
            for (int j = 0; j < 2; j++)
                ldsm_x4_t(bq[j][0], bq[j][1], bq[j][2], bq[j][3],
                          stg + bOff[j] + kk * (LDB * 2));
            #pragma unroll
            for (int mi = 0; mi < 2; mi++)
                #pragma unroll
                for (int ni = 0; ni < 4; ni++)
                    mma16816(acc[mi][ni], af[mi], &bq[ni >> 1][(ni & 1) * 2]);
        }
    }

    // ---- epilogue ----
    float alpha = EPI2 ? g_alpha[g] : 0.f;
    const float* bg = bias + (size_t)g * NTOT;
    #pragma unroll
    for (int mi = 0; mi < 2; mi++) {
        #pragma unroll
        for (int half = 0; half < 2; half++) {
            int rloc = wm + mi * 16 + lrow + half * 8;
            int grow = m0 + rloc;
            if (grow >= cnt) continue;
            #pragma unroll
            for (int ni = 0; ni < 4; ni++) {
                int c = n0 + wn + ni * 8 + lcol;
                float v0 = acc[mi][ni][half * 2 + 0] + bg[c];
                float v1 = acc[mi][ni][half * 2 + 1] + bg[c + 1];
                if (!EPI2) {
                    v0 = fmaxf(v0, 0.f);
                    v1 = fmaxf(v1, 0.f);
                    __nv_bfloat162 pk = __floats2bfloat162_rn(v0, v1);
                    *reinterpret_cast<__nv_bfloat162*>(
                        &g_h[(size_t)(start + grow) * HDIM + c]) = pk;
                } else {
                    int t = g_perm[start + grow];
                    float2 xv = *reinterpret_cast<const float2*>(x + (size_t)t * DDIM + c);
                    float2 o;
                    o.x = xv.x + alpha * v0;
                    o.y = xv.y + alpha * v1;
                    *reinterpret_cast<float2*>(&g_pre[(size_t)t * DDIM + c]) = o;
                }
            }
        }
    }
}

// ---------------- fused persistent kernel: GEMM1 -> GEMM2 -> normalize ----------------
__global__ void __launch_bounds__(256, 3) fused_kernel(
    const float* __restrict__ b1, const float* __restrict__ b2,
    const float* __restrict__ x, float* __restrict__ out)
{
    constexpr int NT1 = HDIM / 128;          // 12
    constexpr int NT2 = DDIM / 128;          // 6
    constexpr int MX  = NTOK / 64;           // 64
    constexpr int T1 = MX * NE * NT1;        // 4608
    constexpr int T2 = MX * NE * NT2;        // 2304
    constexpr int T3 = MX * NE;              // 384
    constexpr int TOTAL = T1 + T2 + T3;

    extern __shared__ __align__(16) unsigned char smem_raw[];
    uint32_t sbase = (uint32_t)__cvta_generic_to_shared(smem_raw);
    int tid = threadIdx.x;

    for (int idx = blockIdx.x; idx < TOTAL; idx += gridDim.x) {
        if (idx < T1) {
            // ---- phase 1: GEMM1 tile ----
            int mx  = idx / (NE * NT1);
            int rem = idx - mx * (NE * NT1);
            int g   = rem / NT1;
            int ny  = rem - g * NT1;
            int start = g_gstart[g];
            int cnt   = g_gstart[g + 1] - start;
            int m0    = mx * 64;
            if (m0 >= cnt) continue;
            gemm_tile<DDIM, false>(smem_raw, sbase, m0, ny * 128, g, start, cnt, b1, x);
            __threadfence();
            __syncthreads();
            if (tid == 0) atomicAdd(&g_c1[g * MX + mx], 1);
        } else if (idx < T1 + T2) {
            // ---- phase 2: GEMM2 tile (waits for all 12 GEMM1 tiles of (g,mx)) ----
            int i2  = idx - T1;
            int mx  = i2 / (NE * NT2);
            int rem = i2 - mx * (NE * NT2);
            int g   = rem / NT2;
            int ny  = rem - g * NT2;
            int start = g_gstart[g];
            int cnt   = g_gstart[g + 1] - start;
            int m0    = mx * 64;
            if (m0 >= cnt) continue;
            if (tid == 0) {
                while (atomicAdd(&g_c1[g * MX + mx], 0) < NT1) __nanosleep(128);
            }
            __syncthreads();
            gemm_tile<HDIM, true>(smem_raw, sbase, m0, ny * 128, g, start, cnt, b2, x);
            __threadfence();
            __syncthreads();
            if (tid == 0) atomicAdd(&g_c2[g * MX + mx], 1);
        } else {
            // ---- phase 3: normalize 64 rows (waits for all 6 GEMM2 tiles of (g,mx)) ----
            int i3 = idx - T1 - T2;
            int mx = i3 / NE;
            int g  = i3 - mx * NE;
            int start = g_gstart[g];
            int cnt   = g_gstart[g + 1] - start;
            int m0    = mx * 64;
            if (m0 >= cnt) continue;
            if (tid == 0) {
                while (atomicAdd(&g_c2[g * MX + mx], 0) < NT2) __nanosleep(128);
            }
            __syncthreads();
            int warp = tid >> 5, lane = tid & 31;
            #pragma unroll
            for (int j = 0; j < 8; j++) {
                int grow = m0 + warp * 8 + j;
                if (grow >= cnt) continue;
                int t = g_perm[start + grow];
                const float4* pr = reinterpret_cast<const float4*>(g_pre + (size_t)t * DDIM);
                float4 v[6];
                float s = 0.f;
                #pragma unroll
                for (int q = 0; q < 6; q++) {
                    v[q] = __ldcg(pr + lane + q * 32);
                    s += v[q].x * v[q].x + v[q].y * v[q].y + v[q].z * v[q].z + v[q].w * v[q].w;
                }
                #pragma unroll
                for (int o = 16; o > 0; o >>= 1) s += __shfl_xor_sync(0xffffffffu, s, o);
                float inv = 1.f / fmaxf(sqrtf(s), 1e-12f);
                float4* po = reinterpret_cast<float4*>(out + (size_t)t * DDIM);
                #pragma unroll
                for (int q = 0; q < 6; q++) {
                    float4 w = v[q];
                    w.x *= inv; w.y *= inv; w.z *= inv; w.w *= inv;
                    po[lane + q * 32] = w;
                }
            }
        }
    }
}

// ---------------- launch: forked-stream graph ----------------
extern "C" void kernel_launch(void* const* d_in, const int* in_sizes, int n_in,
                              void* d_out, int out_size) {
    const float* x         = (const float*)d_in[0];
    const int*   ids       = (const int*)d_in[1];
    const float* W1        = (const float*)d_in[2];
    const float* b1        = (const float*)d_in[3];
    const float* W2        = (const float*)d_in[4];
    const float* b2        = (const float*)d_in[5];
    const float* raw_alpha = (const float*)d_in[6];
    const int*   e2g       = (const int*)d_in[7];
    int T = in_sizes[7];

    constexpr int SMEM_GEMM = (64 * 40 + 32 * 136) * 2 * 3;   // 41472 B

    static cudaStream_t s1 = nullptr, s2 = nullptr;
    static cudaEvent_t  eRoot = nullptr, eW1 = nullptr, eW2 = nullptr;
    static int nblocks = 0;
    if (!s1) {
        cudaStreamCreateWithFlags(&s1, cudaStreamNonBlocking);
        cudaStreamCreateWithFlags(&s2, cudaStreamNonBlocking);
        cudaEventCreateWithFlags(&eRoot, cudaEventDisableTiming);
        cudaEventCreateWithFlags(&eW1,   cudaEventDisableTiming);
        cudaEventCreateWithFlags(&eW2,   cudaEventDisableTiming);
        cudaFuncSetAttribute(fused_kernel,
                             cudaFuncAttributeMaxDynamicSharedMemorySize, SMEM_GEMM);
        int nb = 0, nsm = 0;
        cudaOccupancyMaxActiveBlocksPerMultiprocessor(&nb, fused_kernel, 256, SMEM_GEMM);
        cudaDeviceGetAttribute(&nsm, cudaDevAttrMultiProcessorCount, 0);
        nblocks = nb * nsm;                       // all CTAs co-resident -> spin-safe
        if (nblocks < 1) nblocks = 148;
    }

    // fork
    cudaEventRecord(eRoot, 0);
    cudaStreamWaitEvent(s1, eRoot, 0);
    cudaStreamWaitEvent(s2, eRoot, 0);

    // side branches: weight converts
    convert_kernel<<<1728, 256, 0, s1>>>(W1, 0);
    cudaEventRecord(eW1, s1);
    convert_kernel<<<1728, 256, 0, s2>>>(W2, 1);
    cudaEventRecord(eW2, s2);

    // main branch
    prep_kernel<<<1, 256>>>(ids, e2g, raw_alpha, T);
    gather_kernel<<<3072, 256>>>(x);

    cudaStreamWaitEvent(0, eW1, 0);
    cudaStreamWaitEvent(0, eW2, 0);
    fused_kernel<<<nblocks, 256, SMEM_GEMM>>>(b1, b2, x, (float*)d_out);
}

// round 15
// speedup vs baseline: 1.0170x; 1.0170x over previous
#include <cuda_runtime.h>
#include <cuda_bf16.h>
#include <cstdint>
#include <math.h>

#define NTOK 4096
#define DDIM 768
#define HDIM 1536
#define NE   6
#define NCTA 444   // 148 SMs x 3 CTAs/SM (all co-resident)

// ---------------- device scratch ----------------
__device__ int   g_perm[NTOK];
__device__ int   g_gstart[NE + 1];
__device__ float g_alpha[NE];
__device__ int   g_c2[NE * 64];                              // GEMM2 tile-completion per (g,mx)
__device__ __nv_bfloat16 g_xg[(size_t)NTOK * DDIM];          // gathered x, perm order (bf16)
__device__ __nv_bfloat16 g_h [(size_t)NTOK * HDIM];          // relu hidden, perm order
__device__ __nv_bfloat16 g_W1b[(size_t)NE * DDIM * HDIM];    // bf16 W1, native [e][d][h]
__device__ __nv_bfloat16 g_W2b[(size_t)NE * HDIM * DDIM];    // bf16 W2, native [e][h][d]
__device__ float g_pre[(size_t)NTOK * DDIM];                 // x + alpha*r, token order

// ---------------- asm helpers ----------------
__device__ __forceinline__ void cp_async16(void* smem, const void* g, bool pred) {
    uint32_t s = (uint32_t)__cvta_generic_to_shared(smem);
    int sz = pred ? 16 : 0;   // src-size 0 -> 16B zero-fill
    asm volatile("cp.async.cg.shared.global [%0], [%1], 16, %2;\n" :: "r"(s), "l"(g), "r"(sz));
}
#define CP_COMMIT() asm volatile("cp.async.commit_group;\n" ::: "memory")
#define CP_WAIT1()  asm volatile("cp.async.wait_group 1;\n" ::: "memory")

__device__ __forceinline__ void ldsm_x4(uint32_t& r0, uint32_t& r1, uint32_t& r2, uint32_t& r3,
                                        uint32_t addr) {
    asm volatile("ldmatrix.sync.aligned.m8n8.x4.shared.b16 {%0,%1,%2,%3}, [%4];"
                 : "=r"(r0), "=r"(r1), "=r"(r2), "=r"(r3) : "r"(addr));
}
__device__ __forceinline__ void ldsm_x4_t(uint32_t& r0, uint32_t& r1, uint32_t& r2, uint32_t& r3,
                                          uint32_t addr) {
    asm volatile("ldmatrix.sync.aligned.m8n8.x4.trans.shared.b16 {%0,%1,%2,%3}, [%4];"
                 : "=r"(r0), "=r"(r1), "=r"(r2), "=r"(r3) : "r"(addr));
}

__device__ __forceinline__ void mma16816(float* c, const uint32_t* a, const uint32_t* b) {
    asm volatile(
        "mma.sync.aligned.m16n8k16.row.col.f32.bf16.bf16.f32 "
        "{%0,%1,%2,%3}, {%4,%5,%6,%7}, {%8,%9}, {%0,%1,%2,%3};\n"
        : "+f"(c[0]), "+f"(c[1]), "+f"(c[2]), "+f"(c[3])
        : "r"(a[0]), "r"(a[1]), "r"(a[2]), "r"(a[3]), "r"(b[0]), "r"(b[1]));
}

// ---------------- prep: sort tokens by group + zero counters ----------------
__global__ void prep_kernel(const int* __restrict__ ids,
                            const int* __restrict__ e2g,
                            const float* __restrict__ raw_alpha,
                            int T) {
    __shared__ int cnt[NE];
    __shared__ int cur[NE];
    __shared__ unsigned char gid_s[NTOK];
    int tid = threadIdx.x;
    if (tid < NE) cnt[tid] = 0;
    for (int i = tid; i < NE * 64; i += blockDim.x) g_c2[i] = 0;
    __syncthreads();
    for (int i = tid; i < NTOK; i += blockDim.x) {
        int ty = ids[i];
        ty = ty < 0 ? 0 : (ty > T - 1 ? T - 1 : ty);
        int gd = e2g[ty];
        gid_s[i] = (unsigned char)gd;
        atomicAdd(&cnt[gd], 1);
    }
    __syncthreads();
    if (tid == 0) {
        int acc = 0;
        for (int e = 0; e < NE; e++) { g_gstart[e] = acc; cur[e] = acc; acc += cnt[e]; }
        g_gstart[NE] = acc;
    }
    __syncthreads();
    for (int i = tid; i < NTOK; i += blockDim.x) {
        int pos = atomicAdd(&cur[gid_s[i]], 1);
        g_perm[pos] = i;
    }
    if (tid < NE) g_alpha[tid] = 0.05f / (1.0f + expf(-raw_alpha[tid]));
}

// ---------------- streaming fp32 -> bf16 weight convert ----------------
__global__ void convert_kernel(const float* __restrict__ in, int which) {
    __nv_bfloat16* out = which ? g_W2b : g_W1b;
    size_t i0 = ((size_t)blockIdx.x * 256 + threadIdx.x) * 16;
    #pragma unroll
    for (int h = 0; h < 2; h++) {
        float4 a = *reinterpret_cast<const float4*>(in + i0 + h * 8);
        float4 b = *reinterpret_cast<const float4*>(in + i0 + h * 8 + 4);
        __nv_bfloat162 h0 = __floats2bfloat162_rn(a.x, a.y);
        __nv_bfloat162 h1 = __floats2bfloat162_rn(a.z, a.w);
        __nv_bfloat162 h2 = __floats2bfloat162_rn(b.x, b.y);
        __nv_bfloat162 h3 = __floats2bfloat162_rn(b.z, b.w);
        uint4 o;
        o.x = *reinterpret_cast<uint32_t*>(&h0);
        o.y = *reinterpret_cast<uint32_t*>(&h1);
        o.z = *reinterpret_cast<uint32_t*>(&h2);
        o.w = *reinterpret_cast<uint32_t*>(&h3);
        *reinterpret_cast<uint4*>(out + i0 + h * 8) = o;
    }
}

// ---------------- gather: one float4 per thread ----------------
__global__ void gather_kernel(const float* __restrict__ x) {
    int idx = blockIdx.x * 256 + threadIdx.x;
    int p = idx / 192, j = idx % 192;
    int t = g_perm[p];
    float4 v = *(reinterpret_cast<const float4*>(x + (size_t)t * DDIM) + j);
    __nv_bfloat162 h0 = __floats2bfloat162_rn(v.x, v.y);
    __nv_bfloat162 h1 = __floats2bfloat162_rn(v.z, v.w);
    uint2 o;
    o.x = *reinterpret_cast<uint32_t*>(&h0);
    o.y = *reinterpret_cast<uint32_t*>(&h1);
    *(reinterpret_cast<uint2*>(g_xg + (size_t)p * DDIM) + j) = o;
}

// ---------------- GEMM tile body (BM=64, BN=128, BK=32, 3-stage cp.async) ----------------
template<int K, bool EPI2>
__device__ __forceinline__ void gemm_tile(
    unsigned char* smem_raw, uint32_t sbase,
    int m0, int n0, int g, int start, int cnt,
    const float* __restrict__ bias, const float* __restrict__ x)
{
    constexpr int BM = 64, BN = 128, BK = 32;
    constexpr int LDA = 40;
    constexpr int LDB = 136;
    constexpr int NTOT = EPI2 ? DDIM : HDIM;
    constexpr int NIT  = K / BK;
    constexpr int A_ELEMS = BM * LDA;                 // 2560
    constexpr int STAGE_ELEMS = A_ELEMS + BK * LDB;   // 6912
    constexpr int STAGE_BYTES = STAGE_ELEMS * 2;      // 13824
    constexpr int B_BYTE_OFF  = A_ELEMS * 2;          // 5120

    __nv_bfloat16* smem = reinterpret_cast<__nv_bfloat16*>(smem_raw);
    const __nv_bfloat16* A  = EPI2 ? g_h   : g_xg;
    const __nv_bfloat16* Bw = EPI2 ? g_W2b : g_W1b;
    const __nv_bfloat16* Bg = Bw + (size_t)g * K * NTOT;
    const __nv_bfloat16* Ag = A + (size_t)start * K;

    int tid  = threadIdx.x;
    int warp = tid >> 5, lane = tid & 31;
    int wm = (warp & 1) * 32;
    int wn = (warp >> 1) * 32;
    int lrow = lane >> 2;
    int lcol = (lane & 3) * 2;

    int l15 = lane & 15, lhi = lane >> 4;
    uint32_t aOff[2];
    #pragma unroll
    for (int mi = 0; mi < 2; mi++)
        aOff[mi] = (uint32_t)(((wm + mi * 16 + l15) * LDA + lhi * 8) * 2);
    uint32_t bOff[2];
    #pragma unroll
    for (int j = 0; j < 2; j++)
        bOff[j] = (uint32_t)(B_BYTE_OFF + (l15 * LDB + wn + j * 16 + lhi * 8) * 2);

    auto load_stage = [&](int s, int k0) {
        __nv_bfloat16* As = smem + s * STAGE_ELEMS;
        __nv_bfloat16* Bs = As + A_ELEMS;
        {
            int r = tid >> 2, v = tid & 3;
            bool p = (m0 + r) < cnt;
            int rr = p ? (m0 + r) : 0;
            cp_async16(&As[r * LDA + v * 8], Ag + (size_t)rr * K + k0 + v * 8, p);
        }
        #pragma unroll
        for (int i = 0; i < 2; i++) {
            int c = tid + i * 256;
            int r = c >> 4, v = c & 15;
            cp_async16(&Bs[r * LDB + v * 8],
                       Bg + (size_t)(k0 + r) * NTOT + n0 + v * 8, true);
        }
    };

    float acc[2][4][4];
    #pragma unroll
    for (int mi = 0; mi < 2; mi++)
        #pragma unroll
        for (int ni = 0; ni < 4; ni++)
            #pragma unroll
            for (int qq = 0; qq < 4; qq++) acc[mi][ni][qq] = 0.f;

    // all warps done with previous work-item's smem before refilling
    __syncthreads();

    load_stage(0, 0);
    CP_COMMIT();
    load_stage(1, BK);
    CP_COMMIT();

    for (int it = 0; it < NIT; it++) {
        CP_WAIT1();
        __syncthreads();

        if (it + 2 < NIT) load_stage((it + 2) % 3, (it + 2) * BK);
        CP_COMMIT();

        uint32_t stg = sbase + (uint32_t)((it % 3) * STAGE_BYTES);
        #pragma unroll
        for (int kk = 0; kk < BK; kk += 16) {
            uint32_t af[2][4], bq[2][4];
            #pragma unroll
            for (int mi = 0; mi < 2; mi++)
                ldsm_x4(af[mi][0], af[mi][1], af[mi][2], af[mi][3],
                        stg + aOff[mi] + kk * 2);
            #pragma unroll
            for (int j = 0; j < 2; j++)
                ldsm_x4_t(bq[j][0], bq[j][1], bq[j][2], bq[j][3],
                          stg + bOff[j] + kk * (LDB * 2));
            #pragma unroll
            for (int mi = 0; mi < 2; mi++)
                #pragma unroll
                for (int ni = 0; ni < 4; ni++)
                    mma16816(acc[mi][ni], af[mi], &bq[ni >> 1][(ni & 1) * 2]);
        }
    }

    // ---- epilogue ----
    float alpha = EPI2 ? g_alpha[g] : 0.f;
    const float* bg = bias + (size_t)g * NTOT;
    #pragma unroll
    for (int mi = 0; mi < 2; mi++) {
        #pragma unroll
        for (int half = 0; half < 2; half++) {
            int rloc = wm + mi * 16 + lrow + half * 8;
            int grow = m0 + rloc;
            if (grow >= cnt) continue;
            #pragma unroll
            for (int ni = 0; ni < 4; ni++) {
                int c = n0 + wn + ni * 8 + lcol;
                float v0 = acc[mi][ni][half * 2 + 0] + bg[c];
                float v1 = acc[mi][ni][half * 2 + 1] + bg[c + 1];
                if (!EPI2) {
                    v0 = fmaxf(v0, 0.f);
                    v1 = fmaxf(v1, 0.f);
                    __nv_bfloat162 pk = __floats2bfloat162_rn(v0, v1);
                    *reinterpret_cast<__nv_bfloat162*>(
                        &g_h[(size_t)(start + grow) * HDIM + c]) = pk;
                } else {
                    int t = g_perm[start + grow];
                    float2 xv = *reinterpret_cast<const float2*>(x + (size_t)t * DDIM + c);
                    float2 o;
                    o.x = xv.x + alpha * v0;
                    o.y = xv.y + alpha * v1;
                    *reinterpret_cast<float2*>(&g_pre[(size_t)t * DDIM + c]) = o;
                }
            }
        }
    }
}

// ---------------- persistent GEMM1 (R13 structure) ----------------
__global__ void __launch_bounds__(256, 3) gemm1_kernel(
    const float* __restrict__ bias, const float* __restrict__ x)
{
    constexpr int NT = HDIM / 128;          // 12
    constexpr int PER_X = NE * NT;          // 72
    constexpr int TOTAL = (NTOK / 64) * PER_X;   // 4608

    extern __shared__ __align__(16) unsigned char smem_raw[];
    uint32_t sbase = (uint32_t)__cvta_generic_to_shared(smem_raw);

    for (int idx = blockIdx.x; idx < TOTAL; idx += NCTA) {
        int mx  = idx / PER_X;
        int rem = idx - mx * PER_X;
        int g   = rem / NT;
        int ny  = rem - g * NT;
        int start = g_gstart[g];
        int cnt   = g_gstart[g + 1] - start;
        int m0    = mx * 64;
        if (m0 >= cnt) continue;
        gemm_tile<DDIM, false>(smem_raw, sbase, m0, ny * 128, g, start, cnt, bias, x);
    }
}

// ---------------- persistent fused GEMM2 + normalize ----------------
__global__ void __launch_bounds__(256, 3) gemm2norm_kernel(
    const float* __restrict__ bias, const float* __restrict__ x,
    float* __restrict__ out)
{
    constexpr int NT = DDIM / 128;          // 6
    constexpr int MX = NTOK / 64;           // 64
    constexpr int T2 = MX * NE * NT;        // 2304
    constexpr int T3 = MX * NE;             // 384
    constexpr int TOTAL = T2 + T3;

    extern __shared__ __align__(16) unsigned char smem_raw[];
    uint32_t sbase = (uint32_t)__cvta_generic_to_shared(smem_raw);
    int tid = threadIdx.x;

    for (int idx = blockIdx.x; idx < TOTAL; idx += NCTA) {
        if (idx < T2) {
            // ---- GEMM2 tile ----
            int mx  = idx / (NE * NT);
            int rem = idx - mx * (NE * NT);
            int g   = rem / NT;
            int ny  = rem - g * NT;
            int start = g_gstart[g];
            int cnt   = g_gstart[g + 1] - start;
            int m0    = mx * 64;
            if (m0 >= cnt) continue;
            gemm_tile<HDIM, true>(smem_raw, sbase, m0, ny * 128, g, start, cnt, bias, x);
            __threadfence();
            __syncthreads();
            if (tid == 0) atomicAdd(&g_c2[g * MX + mx], 1);
        } else {
            // ---- normalize 64 rows (waits for all 6 GEMM2 tiles of (g,mx)) ----
            int i3 = idx - T2;
            int mx = i3 / NE;
            int g  = i3 - mx * NE;
            int start = g_gstart[g];
            int cnt   = g_gstart[g + 1] - start;
            int m0    = mx * 64;
            if (m0 >= cnt) continue;
            if (tid == 0) {
                while (atomicAdd(&g_c2[g * MX + mx], 0) < NT) __nanosleep(64);
            }
            __syncthreads();
            __threadfence();
            int warp = tid >> 5, lane = tid & 31;
            #pragma unroll
            for (int j = 0; j < 8; j++) {
                int grow = m0 + warp * 8 + j;
                if (grow >= cnt) continue;
                int t = g_perm[start + grow];
                const float4* pr = reinterpret_cast<const float4*>(g_pre + (size_t)t * DDIM);
                float4 v[6];
                float s = 0.f;
                #pragma unroll
                for (int q = 0; q < 6; q++) {
                    v[q] = __ldcg(pr + lane + q * 32);
                    s += v[q].x * v[q].x + v[q].y * v[q].y + v[q].z * v[q].z + v[q].w * v[q].w;
                }
                #pragma unroll
                for (int o = 16; o > 0; o >>= 1) s += __shfl_xor_sync(0xffffffffu, s, o);
                float inv = 1.f / fmaxf(sqrtf(s), 1e-12f);
                float4* po = reinterpret_cast<float4*>(out + (size_t)t * DDIM);
                #pragma unroll
                for (int q = 0; q < 6; q++) {
                    float4 w = v[q];
                    w.x *= inv; w.y *= inv; w.z *= inv; w.w *= inv;
                    po[lane + q * 32] = w;
                }
            }
        }
    }
}

// ---------------- launch: forked-stream graph ----------------
extern "C" void kernel_launch(void* const* d_in, const int* in_sizes, int n_in,
                              void* d_out, int out_size) {
    const float* x         = (const float*)d_in[0];
    const int*   ids       = (const int*)d_in[1];
    const float* W1        = (const float*)d_in[2];
    const float* b1        = (const float*)d_in[3];
    const float* W2        = (const float*)d_in[4];
    const float* b2        = (const float*)d_in[5];
    const float* raw_alpha = (const float*)d_in[6];
    const int*   e2g       = (const int*)d_in[7];
    int T = in_sizes[7];

    constexpr int SMEM_GEMM = (64 * 40 + 32 * 136) * 2 * 3;   // 41472 B

    static cudaStream_t s1 = nullptr, s2 = nullptr;
    static cudaEvent_t  eRoot = nullptr, eW1 = nullptr, eW2 = nullptr;
    if (!s1) {
        cudaStreamCreateWithFlags(&s1, cudaStreamNonBlocking);
        cudaStreamCreateWithFlags(&s2, cudaStreamNonBlocking);
        cudaEventCreateWithFlags(&eRoot, cudaEventDisableTiming);
        cudaEventCreateWithFlags(&eW1,   cudaEventDisableTiming);
        cudaEventCreateWithFlags(&eW2,   cudaEventDisableTiming);
        cudaFuncSetAttribute(gemm1_kernel,
                             cudaFuncAttributeMaxDynamicSharedMemorySize, SMEM_GEMM);
        cudaFuncSetAttribute(gemm2norm_kernel,
                             cudaFuncAttributeMaxDynamicSharedMemorySize, SMEM_GEMM);
    }

    // fork
    cudaEventRecord(eRoot, 0);
    cudaStreamWaitEvent(s1, eRoot, 0);
    cudaStreamWaitEvent(s2, eRoot, 0);

    // side branches: weight converts
    convert_kernel<<<1728, 256, 0, s1>>>(W1, 0);
    cudaEventRecord(eW1, s1);
    convert_kernel<<<1728, 256, 0, s2>>>(W2, 1);
    cudaEventRecord(eW2, s2);

    // main branch
    prep_kernel<<<1, 256>>>(ids, e2g, raw_alpha, T);
    gather_kernel<<<3072, 256>>>(x);

    cudaStreamWaitEvent(0, eW1, 0);
    gemm1_kernel<<<NCTA, 256, SMEM_GEMM>>>(b1, x);

    cudaStreamWaitEvent(0, eW2, 0);
    gemm2norm_kernel<<<NCTA, 256, SMEM_GEMM>>>(b2, x, (float*)d_out);
}

// round 16
// speedup vs baseline: 1.0535x; 1.0360x over previous
#include <cuda_runtime.h>
#include <cuda_bf16.h>
#include <cstdint>
#include <math.h>

#define NTOK 4096
#define DDIM 768
#define HDIM 1536
#define NE   6
#define NCTA 444   // 148 SMs x 3 CTAs/SM

// ---------------- device scratch ----------------
__device__ int   g_perm[NTOK];
__device__ int   g_gstart[NE + 1];
__device__ float g_alpha[NE];
__device__ __nv_bfloat16 g_xg[(size_t)NTOK * DDIM];          // gathered x, perm order (bf16)
__device__ __nv_bfloat16 g_h [(size_t)NTOK * HDIM];          // relu hidden, perm order
__device__ __nv_bfloat16 g_W1b[(size_t)NE * DDIM * HDIM];    // bf16 W1, native [e][d][h]
__device__ __nv_bfloat16 g_W2b[(size_t)NE * HDIM * DDIM];    // bf16 W2, native [e][h][d]
__device__ float g_pre[(size_t)NTOK * DDIM];                 // x + alpha*r, token order

// ---------------- asm helpers ----------------
__device__ __forceinline__ void cp_async16(void* smem, const void* g, bool pred) {
    uint32_t s = (uint32_t)__cvta_generic_to_shared(smem);
    int sz = pred ? 16 : 0;   // src-size 0 -> 16B zero-fill
    asm volatile("cp.async.cg.shared.global [%0], [%1], 16, %2;\n" :: "r"(s), "l"(g), "r"(sz));
}
#define CP_COMMIT() asm volatile("cp.async.commit_group;\n" ::: "memory")
#define CP_WAIT1()  asm volatile("cp.async.wait_group 1;\n" ::: "memory")

__device__ __forceinline__ void ldsm_x4(uint32_t& r0, uint32_t& r1, uint32_t& r2, uint32_t& r3,
                                        uint32_t addr) {
    asm volatile("ldmatrix.sync.aligned.m8n8.x4.shared.b16 {%0,%1,%2,%3}, [%4];"
                 : "=r"(r0), "=r"(r1), "=r"(r2), "=r"(r3) : "r"(addr));
}
__device__ __forceinline__ void ldsm_x4_t(uint32_t& r0, uint32_t& r1, uint32_t& r2, uint32_t& r3,
                                          uint32_t addr) {
    asm volatile("ldmatrix.sync.aligned.m8n8.x4.trans.shared.b16 {%0,%1,%2,%3}, [%4];"
                 : "=r"(r0), "=r"(r1), "=r"(r2), "=r"(r3) : "r"(addr));
}

__device__ __forceinline__ void mma16816(float* c, const uint32_t* a, const uint32_t* b) {
    asm volatile(
        "mma.sync.aligned.m16n8k16.row.col.f32.bf16.bf16.f32 "
        "{%0,%1,%2,%3}, {%4,%5,%6,%7}, {%8,%9}, {%0,%1,%2,%3};\n"
        : "+f"(c[0]), "+f"(c[1]), "+f"(c[2]), "+f"(c[3])
        : "r"(a[0]), "r"(a[1]), "r"(a[2]), "r"(a[3]), "r"(b[0]), "r"(b[1]));
}

// ---------------- prep: sort tokens by group ----------------
__global__ void prep_kernel(const int* __restrict__ ids,
                            const int* __restrict__ e2g,
                            const float* __restrict__ raw_alpha,
                            int T) {
    __shared__ int cnt[NE];
    __shared__ int cur[NE];
    __shared__ unsigned char gid_s[NTOK];
    int tid = threadIdx.x;
    if (tid < NE) cnt[tid] = 0;
    __syncthreads();
    for (int i = tid; i < NTOK; i += blockDim.x) {
        int ty = ids[i];
        ty = ty < 0 ? 0 : (ty > T - 1 ? T - 1 : ty);
        int gd = e2g[ty];
        gid_s[i] = (unsigned char)gd;
        atomicAdd(&cnt[gd], 1);
    }
    __syncthreads();
    if (tid == 0) {
        int acc = 0;
        for (int e = 0; e < NE; e++) { g_gstart[e] = acc; cur[e] = acc; acc += cnt[e]; }
        g_gstart[NE] = acc;
    }
    __syncthreads();
    for (int i = tid; i < NTOK; i += blockDim.x) {
        int pos = atomicAdd(&cur[gid_s[i]], 1);
        g_perm[pos] = i;
    }
    if (tid < NE) g_alpha[tid] = 0.05f / (1.0f + expf(-raw_alpha[tid]));
}

// ---------------- streaming fp32 -> bf16 weight convert (16 elems/thread) ----------------
__global__ void convert_kernel(const float* __restrict__ in, int which) {
    __nv_bfloat16* out = which ? g_W2b : g_W1b;
    size_t i0 = ((size_t)blockIdx.x * 256 + threadIdx.x) * 16;
    #pragma unroll
    for (int h = 0; h < 2; h++) {
        float4 a = *reinterpret_cast<const float4*>(in + i0 + h * 8);
        float4 b = *reinterpret_cast<const float4*>(in + i0 + h * 8 + 4);
        __nv_bfloat162 h0 = __floats2bfloat162_rn(a.x, a.y);
        __nv_bfloat162 h1 = __floats2bfloat162_rn(a.z, a.w);
        __nv_bfloat162 h2 = __floats2bfloat162_rn(b.x, b.y);
        __nv_bfloat162 h3 = __floats2bfloat162_rn(b.z, b.w);
        uint4 o;
        o.x = *reinterpret_cast<uint32_t*>(&h0);
        o.y = *reinterpret_cast<uint32_t*>(&h1);
        o.z = *reinterpret_cast<uint32_t*>(&h2);
        o.w = *reinterpret_cast<uint32_t*>(&h3);
        *reinterpret_cast<uint4*>(out + i0 + h * 8) = o;
    }
}

// ---------------- gather: one float4 per thread ----------------
__global__ void gather_kernel(const float* __restrict__ x) {
    int idx = blockIdx.x * 256 + threadIdx.x;
    int p = idx / 192, j = idx % 192;
    int t = g_perm[p];
    float4 v = *(reinterpret_cast<const float4*>(x + (size_t)t * DDIM) + j);
    __nv_bfloat162 h0 = __floats2bfloat162_rn(v.x, v.y);
    __nv_bfloat162 h1 = __floats2bfloat162_rn(v.z, v.w);
    uint2 o;
    o.x = *reinterpret_cast<uint32_t*>(&h0);
    o.y = *reinterpret_cast<uint32_t*>(&h1);
    *(reinterpret_cast<uint2*>(g_xg + (size_t)p * DDIM) + j) = o;
}

// ---------------- persistent grouped GEMM: BM=64, 3-stage cp.async, tile loop ----------------
// EPI2 == false : g_h[p,:] = relu(g_xg[p,:] @ W1[g] + b1[g])   bf16 out
// EPI2 == true  : g_pre[t,:] = x[t,:] + alpha[g] * (g_h[p,:] @ W2[g] + b2[g])
template<int K, bool EPI2>
__global__ void __launch_bounds__(256, 3) gemm_kernel(
    const float* __restrict__ bias,        // [E][NTOT] fp32
    const float* __restrict__ x)
{
    constexpr int BM = 64, BN = 128, BK = 32;
    constexpr int LDA = 40;
    constexpr int LDB = 136;
    constexpr int NTOT = EPI2 ? DDIM : HDIM;
    constexpr int NIT  = K / BK;            // 24 or 48 (divisible by 3 -> safe stage reuse)
    constexpr int NT   = NTOT / BN;         // n-tiles: 6 or 12
    constexpr int PER_X = NE * NT;          // logical tiles per m-tile index
    constexpr int TOTAL = (NTOK / BM) * PER_X;
    constexpr int A_ELEMS = BM * LDA;                 // 2560
    constexpr int STAGE_ELEMS = A_ELEMS + BK * LDB;   // 6912
    constexpr int STAGE_BYTES = STAGE_ELEMS * 2;      // 13824
    constexpr int B_BYTE_OFF  = A_ELEMS * 2;          // 5120

    extern __shared__ __align__(16) unsigned char smem_raw[];
    __nv_bfloat16* smem = reinterpret_cast<__nv_bfloat16*>(smem_raw);
    uint32_t sbase = (uint32_t)__cvta_generic_to_shared(smem_raw);

    const __nv_bfloat16* A  = EPI2 ? g_h   : g_xg;
    const __nv_bfloat16* Bw = EPI2 ? g_W2b : g_W1b;

    int tid  = threadIdx.x;
    int warp = tid >> 5, lane = tid & 31;
    int wm = (warp & 1) * 32;       // 2 warps over M
    int wn = (warp >> 1) * 32;      // 4 warps over N
    int lrow = lane >> 2;
    int lcol = (lane & 3) * 2;

    int l15 = lane & 15, lhi = lane >> 4;
    uint32_t aOff[2];
    #pragma unroll
    for (int mi = 0; mi < 2; mi++)
        aOff[mi] = (uint32_t)(((wm + mi * 16 + l15) * LDA + lhi * 8) * 2);
    uint32_t bOff[2];
    #pragma unroll
    for (int j = 0; j < 2; j++)
        bOff[j] = (uint32_t)(B_BYTE_OFF + (l15 * LDB + wn + j * 16 + lhi * 8) * 2);

    for (int idx = blockIdx.x; idx < TOTAL; idx += NCTA) {
        int mx  = idx / PER_X;
        int rem = idx - mx * PER_X;
        int g   = rem / NT;
        int ny  = rem - g * NT;

        int start = g_gstart[g];
        int cnt   = g_gstart[g + 1] - start;
        int m0    = mx * BM;
        if (m0 >= cnt) continue;
        int n0 = ny * BN;
        const __nv_bfloat16* Bg = Bw + (size_t)g * K * NTOT;
        const __nv_bfloat16* Ag = A + (size_t)start * K;

        auto load_stage = [&](int s, int k0) {
            __nv_bfloat16* As = smem + s * STAGE_ELEMS;
            __nv_bfloat16* Bs = As + A_ELEMS;
            {
                int r = tid >> 2, v = tid & 3;
                bool p = (m0 + r) < cnt;
                int rr = p ? (m0 + r) : 0;
                cp_async16(&As[r * LDA + v * 8], Ag + (size_t)rr * K + k0 + v * 8, p);
            }
            #pragma unroll
            for (int i = 0; i < 2; i++) {
                int c = tid + i * 256;
                int r = c >> 4, v = c & 15;
                cp_async16(&Bs[r * LDB + v * 8],
                           Bg + (size_t)(k0 + r) * NTOT + n0 + v * 8, true);
            }
        };

        float acc[2][4][4];
        #pragma unroll
        for (int mi = 0; mi < 2; mi++)
            #pragma unroll
            for (int ni = 0; ni < 4; ni++)
                #pragma unroll
                for (int qq = 0; qq < 4; qq++) acc[mi][ni][qq] = 0.f;

        // all warps must be done with the previous tile's smem before refilling
        __syncthreads();

        load_stage(0, 0);
        CP_COMMIT();
        load_stage(1, BK);
        CP_COMMIT();

        for (int it = 0; it < NIT; it++) {
            CP_WAIT1();
            __syncthreads();

            if (it + 2 < NIT) load_stage((it + 2) % 3, (it + 2) * BK);
            CP_COMMIT();

            uint32_t stg = sbase + (uint32_t)((it % 3) * STAGE_BYTES);
            #pragma unroll
            for (int kk = 0; kk < BK; kk += 16) {
                uint32_t af[2][4], bq[2][4];
                #pragma unroll
                for (int mi = 0; mi < 2; mi++)
                    ldsm_x4(af[mi][0], af[mi][1], af[mi][2], af[mi][3],
                            stg + aOff[mi] + kk * 2);
                #pragma unroll
                for (int j = 0; j < 2; j++)
                    ldsm_x4_t(bq[j][0], bq[j][1], bq[j][2], bq[j][3],
                              stg + bOff[j] + kk * (LDB * 2));
                #pragma unroll
                for (int mi = 0; mi < 2; mi++)
                    #pragma unroll
                    for (int ni = 0; ni < 4; ni++)
                        mma16816(acc[mi][ni], af[mi], &bq[ni >> 1][(ni & 1) * 2]);
            }
        }

        // ---- epilogue ----
        float alpha = EPI2 ? g_alpha[g] : 0.f;
        const float* bg = bias + (size_t)g * NTOT;
        #pragma unroll
        for (int mi = 0; mi < 2; mi++) {
            #pragma unroll
            for (int half = 0; half < 2; half++) {
                int rloc = wm + mi * 16 + lrow + half * 8;
                int grow = m0 + rloc;
                if (grow >= cnt) continue;
                #pragma unroll
                for (int ni = 0; ni < 4; ni++) {
                    int c = n0 + wn + ni * 8 + lcol;
                    float v0 = acc[mi][ni][half * 2 + 0] + bg[c];
                    float v1 = acc[mi][ni][half * 2 + 1] + bg[c + 1];
                    if (!EPI2) {
                        v0 = fmaxf(v0, 0.f);
                        v1 = fmaxf(v1, 0.f);
                        __nv_bfloat162 pk = __floats2bfloat162_rn(v0, v1);
                        *reinterpret_cast<__nv_bfloat162*>(
                            &g_h[(size_t)(start + grow) * HDIM + c]) = pk;
                    } else {
                        int t = g_perm[start + grow];
                        float2 xv = *reinterpret_cast<const float2*>(x + (size_t)t * DDIM + c);
                        float2 o;
                        o.x = xv.x + alpha * v0;
                        o.y = xv.y + alpha * v1;
                        *reinterpret_cast<float2*>(&g_pre[(size_t)t * DDIM + c]) = o;
                    }
                }
            }
        }
    }
}

// ---------------- normalize: warp-per-row, no block sync ----------------
// 512 blocks x 256 threads = 4096 warps = 4096 rows
__global__ void normalize_kernel(float* __restrict__ out) {
    int warp = threadIdx.x >> 5, lane = threadIdx.x & 31;
    int t = blockIdx.x * 8 + warp;
    const float4* pr = reinterpret_cast<const float4*>(g_pre + (size_t)t * DDIM);
    float4 v[6];
    float s = 0.f;
    #pragma unroll
    for (int q = 0; q < 6; q++) {
        v[q] = pr[lane + q * 32];
        s += v[q].x * v[q].x + v[q].y * v[q].y + v[q].z * v[q].z + v[q].w * v[q].w;
    }
    #pragma unroll
    for (int o = 16; o > 0; o >>= 1) s += __shfl_xor_sync(0xffffffffu, s, o);
    float inv = 1.f / fmaxf(sqrtf(s), 1e-12f);
    float4* po = reinterpret_cast<float4*>(out + (size_t)t * DDIM);
    #pragma unroll
    for (int q = 0; q < 6; q++) {
        float4 w = v[q];
        w.x *= inv; w.y *= inv; w.z *= inv; w.w *= inv;
        po[lane + q * 32] = w;
    }
}

// ---------------- launch: forked-stream graph ----------------
extern "C" void kernel_launch(void* const* d_in, const int* in_sizes, int n_in,
                              void* d_out, int out_size) {
    const float* x         = (const float*)d_in[0];
    const int*   ids       = (const int*)d_in[1];
    const float* W1        = (const float*)d_in[2];
    const float* b1        = (const float*)d_in[3];
    const float* W2        = (const float*)d_in[4];
    const float* b2        = (const float*)d_in[5];
    const float* raw_alpha = (const float*)d_in[6];
    const int*   e2g       = (const int*)d_in[7];
    int T = in_sizes[7];

    static cudaStream_t s1 = nullptr, s2 = nullptr;
    static cudaEvent_t  eRoot = nullptr, eW1 = nullptr, eW2 = nullptr;
    static bool smem_set = false;
    if (!s1) {
        cudaStreamCreateWithFlags(&s1, cudaStreamNonBlocking);
        cudaStreamCreateWithFlags(&s2, cudaStreamNonBlocking);
        cudaEventCreateWithFlags(&eRoot, cudaEventDisableTiming);
        cudaEventCreateWithFlags(&eW1,   cudaEventDisableTiming);
        cudaEventCreateWithFlags(&eW2,   cudaEventDisableTiming);
    }
    constexpr int SMEM_GEMM = (64 * 40 + 32 * 136) * 2 * 3;   // 41472 B
    if (!smem_set) {
        cudaFuncSetAttribute(gemm_kernel<DDIM, false>,
                             cudaFuncAttributeMaxDynamicSharedMemorySize, SMEM_GEMM);
        cudaFuncSetAttribute(gemm_kernel<HDIM, true>,
                             cudaFuncAttributeMaxDynamicSharedMemorySize, SMEM_GEMM);
        smem_set = true;
    }

    // fork
    cudaEventRecord(eRoot, 0);
    cudaStreamWaitEvent(s1, eRoot, 0);
    cudaStreamWaitEvent(s2, eRoot, 0);

    // side branches: weight converts
    convert_kernel<<<1728, 256, 0, s1>>>(W1, 0);
    cudaEventRecord(eW1, s1);
    convert_kernel<<<1728, 256, 0, s2>>>(W2, 1);
    cudaEventRecord(eW2, s2);

    // main branch
    prep_kernel<<<1, 256>>>(ids, e2g, raw_alpha, T);
    gather_kernel<<<3072, 256>>>(x);

    cudaStreamWaitEvent(0, eW1, 0);
    gemm_kernel<DDIM, false><<<NCTA, 256, SMEM_GEMM>>>(b1, x);

    cudaStreamWaitEvent(0, eW2, 0);
    gemm_kernel<HDIM, true ><<<NCTA, 256, SMEM_GEMM>>>(b2, x);

    normalize_kernel<<<512, 256>>>((float*)d_out);
}

// round 17
// speedup vs baseline: 1.0727x; 1.0182x over previous
#include <cuda_runtime.h>
#include <cuda_bf16.h>
#include <cstdint>
#include <math.h>

#define NTOK 4096
#define DDIM 768
#define HDIM 1536
#define NE   6
#define NCTA 444   // 148 SMs x 3 CTAs/SM

// ---------------- device scratch ----------------
__device__ int   g_perm[NTOK];
__device__ int   g_gstart[NE + 1];
__device__ float g_alpha[NE];
__device__ __nv_bfloat16 g_xg[(size_t)NTOK * DDIM];          // gathered x, perm order (bf16)
__device__ __nv_bfloat16 g_h [(size_t)NTOK * HDIM];          // relu hidden, perm order
__device__ __nv_bfloat16 g_W1b[(size_t)NE * DDIM * HDIM];    // bf16 W1, native [e][d][h]
__device__ __nv_bfloat16 g_W2b[(size_t)NE * HDIM * DDIM];    // bf16 W2, native [e][h][d]
__device__ float g_pre[(size_t)NTOK * DDIM];                 // x + alpha*r, token order

// ---------------- asm helpers ----------------
__device__ __forceinline__ void cp_async16(void* smem, const void* g, bool pred) {
    uint32_t s = (uint32_t)__cvta_generic_to_shared(smem);
    int sz = pred ? 16 : 0;   // src-size 0 -> 16B zero-fill
    asm volatile("cp.async.cg.shared.global [%0], [%1], 16, %2;\n" :: "r"(s), "l"(g), "r"(sz));
}
#define CP_COMMIT() asm volatile("cp.async.commit_group;\n" ::: "memory")
#define CP_WAIT1()  asm volatile("cp.async.wait_group 1;\n" ::: "memory")

__device__ __forceinline__ void ldsm_x4(uint32_t& r0, uint32_t& r1, uint32_t& r2, uint32_t& r3,
                                        uint32_t addr) {
    asm volatile("ldmatrix.sync.aligned.m8n8.x4.shared.b16 {%0,%1,%2,%3}, [%4];"
                 : "=r"(r0), "=r"(r1), "=r"(r2), "=r"(r3) : "r"(addr));
}
__device__ __forceinline__ void ldsm_x4_t(uint32_t& r0, uint32_t& r1, uint32_t& r2, uint32_t& r3,
                                          uint32_t addr) {
    asm volatile("ldmatrix.sync.aligned.m8n8.x4.trans.shared.b16 {%0,%1,%2,%3}, [%4];"
                 : "=r"(r0), "=r"(r1), "=r"(r2), "=r"(r3) : "r"(addr));
}

__device__ __forceinline__ void mma16816(float* c, const uint32_t* a, const uint32_t* b) {
    asm volatile(
        "mma.sync.aligned.m16n8k16.row.col.f32.bf16.bf16.f32 "
        "{%0,%1,%2,%3}, {%4,%5,%6,%7}, {%8,%9}, {%0,%1,%2,%3};\n"
        : "+f"(c[0]), "+f"(c[1]), "+f"(c[2]), "+f"(c[3])
        : "r"(a[0]), "r"(a[1]), "r"(a[2]), "r"(a[3]), "r"(b[0]), "r"(b[1]));
}

// ---------------- prep: sort tokens by group (1024 threads) ----------------
__global__ void prep_kernel(const int* __restrict__ ids,
                            const int* __restrict__ e2g,
                            const float* __restrict__ raw_alpha,
                            int T) {
    __shared__ int cnt[NE];
    __shared__ int cur[NE];
    __shared__ unsigned char gid_s[NTOK];
    int tid = threadIdx.x;
    if (tid < NE) cnt[tid] = 0;
    __syncthreads();
    for (int i = tid; i < NTOK; i += blockDim.x) {
        int ty = ids[i];
        ty = ty < 0 ? 0 : (ty > T - 1 ? T - 1 : ty);
        int gd = e2g[ty];
        gid_s[i] = (unsigned char)gd;
        atomicAdd(&cnt[gd], 1);
    }
    __syncthreads();
    if (tid == 0) {
        int acc = 0;
        for (int e = 0; e < NE; e++) { g_gstart[e] = acc; cur[e] = acc; acc += cnt[e]; }
        g_gstart[NE] = acc;
    }
    __syncthreads();
    for (int i = tid; i < NTOK; i += blockDim.x) {
        int pos = atomicAdd(&cur[gid_s[i]], 1);
        g_perm[pos] = i;
    }
    if (tid < NE) g_alpha[tid] = 0.05f / (1.0f + expf(-raw_alpha[tid]));
}

// ---------------- streaming fp32 -> bf16 weight convert (16 elems/thread, split-able) ----------------
__global__ void convert_kernel(const float* __restrict__ in, int which, int blkoff) {
    __nv_bfloat16* out = which ? g_W2b : g_W1b;
    size_t i0 = ((size_t)(blockIdx.x + blkoff) * 256 + threadIdx.x) * 16;
    #pragma unroll
    for (int h = 0; h < 2; h++) {
        float4 a = *reinterpret_cast<const float4*>(in + i0 + h * 8);
        float4 b = *reinterpret_cast<const float4*>(in + i0 + h * 8 + 4);
        __nv_bfloat162 h0 = __floats2bfloat162_rn(a.x, a.y);
        __nv_bfloat162 h1 = __floats2bfloat162_rn(a.z, a.w);
        __nv_bfloat162 h2 = __floats2bfloat162_rn(b.x, b.y);
        __nv_bfloat162 h3 = __floats2bfloat162_rn(b.z, b.w);
        uint4 o;
        o.x = *reinterpret_cast<uint32_t*>(&h0);
        o.y = *reinterpret_cast<uint32_t*>(&h1);
        o.z = *reinterpret_cast<uint32_t*>(&h2);
        o.w = *reinterpret_cast<uint32_t*>(&h3);
        *reinterpret_cast<uint4*>(out + i0 + h * 8) = o;
    }
}

// ---------------- gather: 8 floats per thread (2x float4 LDG -> 1x uint4 STG) ----------------
// 1536 blocks x 256 threads = 393216 = 4096 rows x 96 8-float chunks
__global__ void gather_kernel(const float* __restrict__ x) {
    int idx = blockIdx.x * 256 + threadIdx.x;
    int p = idx / 96, j = idx % 96;
    int t = g_perm[p];
    const float4* src = reinterpret_cast<const float4*>(x + (size_t)t * DDIM) + j * 2;
    float4 a = src[0];
    float4 b = src[1];
    __nv_bfloat162 h0 = __floats2bfloat162_rn(a.x, a.y);
    __nv_bfloat162 h1 = __floats2bfloat162_rn(a.z, a.w);
    __nv_bfloat162 h2 = __floats2bfloat162_rn(b.x, b.y);
    __nv_bfloat162 h3 = __floats2bfloat162_rn(b.z, b.w);
    uint4 o;
    o.x = *reinterpret_cast<uint32_t*>(&h0);
    o.y = *reinterpret_cast<uint32_t*>(&h1);
    o.z = *reinterpret_cast<uint32_t*>(&h2);
    o.w = *reinterpret_cast<uint32_t*>(&h3);
    *(reinterpret_cast<uint4*>(g_xg + (size_t)p * DDIM) + j) = o;
}

// ---------------- persistent grouped GEMM: BM=64, 3-stage cp.async, tile loop ----------------
// EPI2 == false : g_h[p,:] = relu(g_xg[p,:] @ W1[g] + b1[g])   bf16 out
// EPI2 == true  : g_pre[t,:] = x[t,:] + alpha[g] * (g_h[p,:] @ W2[g] + b2[g])
template<int K, bool EPI2>
__global__ void __launch_bounds__(256, 3) gemm_kernel(
    const float* __restrict__ bias,        // [E][NTOT] fp32
    const float* __restrict__ x)
{
    constexpr int BM = 64, BN = 128, BK = 32;
    constexpr int LDA = 40;
    constexpr int LDB = 136;
    constexpr int NTOT = EPI2 ? DDIM : HDIM;
    constexpr int NIT  = K / BK;
    constexpr int NT   = NTOT / BN;
    constexpr int PER_X = NE * NT;
    constexpr int TOTAL = (NTOK / BM) * PER_X;
    constexpr int A_ELEMS = BM * LDA;                 // 2560
    constexpr int STAGE_ELEMS = A_ELEMS + BK * LDB;   // 6912
    constexpr int STAGE_BYTES = STAGE_ELEMS * 2;      // 13824
    constexpr int B_BYTE_OFF  = A_ELEMS * 2;          // 5120

    extern __shared__ __align__(16) unsigned char smem_raw[];
    __nv_bfloat16* smem = reinterpret_cast<__nv_bfloat16*>(smem_raw);
    uint32_t sbase = (uint32_t)__cvta_generic_to_shared(smem_raw);

    const __nv_bfloat16* A  = EPI2 ? g_h   : g_xg;
    const __nv_bfloat16* Bw = EPI2 ? g_W2b : g_W1b;

    int tid  = threadIdx.x;
    int warp = tid >> 5, lane = tid & 31;
    int wm = (warp & 1) * 32;       // 2 warps over M
    int wn = (warp >> 1) * 32;      // 4 warps over N
    int lrow = lane >> 2;
    int lcol = (lane & 3) * 2;

    int l15 = lane & 15, lhi = lane >> 4;
    uint32_t aOff[2];
    #pragma unroll
    for (int mi = 0; mi < 2; mi++)
        aOff[mi] = (uint32_t)(((wm + mi * 16 + l15) * LDA + lhi * 8) * 2);
    uint32_t bOff[2];
    #pragma unroll
    for (int j = 0; j < 2; j++)
        bOff[j] = (uint32_t)(B_BYTE_OFF + (l15 * LDB + wn + j * 16 + lhi * 8) * 2);

    for (int idx = blockIdx.x; idx < TOTAL; idx += NCTA) {
        int mx  = idx / PER_X;
        int rem = idx - mx * PER_X;
        int g   = rem / NT;
        int ny  = rem - g * NT;

        int start = g_gstart[g];
        int cnt   = g_gstart[g + 1] - start;
        int m0    = mx * BM;
        if (m0 >= cnt) continue;
        int n0 = ny * BN;
        const __nv_bfloat16* Bg = Bw + (size_t)g * K * NTOT;
        const __nv_bfloat16* Ag = A + (size_t)start * K;

        auto load_stage = [&](int s, int k0) {
            __nv_bfloat16* As = smem + s * STAGE_ELEMS;
            __nv_bfloat16* Bs = As + A_ELEMS;
            {
                int r = tid >> 2, v = tid & 3;
                bool p = (m0 + r) < cnt;
                int rr = p ? (m0 + r) : 0;
                cp_async16(&As[r * LDA + v * 8], Ag + (size_t)rr * K + k0 + v * 8, p);
            }
            #pragma unroll
            for (int i = 0; i < 2; i++) {
                int c = tid + i * 256;
                int r = c >> 4, v = c & 15;
                cp_async16(&Bs[r * LDB + v * 8],
                           Bg + (size_t)(k0 + r) * NTOT + n0 + v * 8, true);
            }
        };

        float acc[2][4][4];
        #pragma unroll
        for (int mi = 0; mi < 2; mi++)
            #pragma unroll
            for (int ni = 0; ni < 4; ni++)
                #pragma unroll
                for (int qq = 0; qq < 4; qq++) acc[mi][ni][qq] = 0.f;

        // all warps must be done with the previous tile's smem before refilling
        __syncthreads();

        load_stage(0, 0);
        CP_COMMIT();
        load_stage(1, BK);
        CP_COMMIT();

        for (int it = 0; it < NIT; it++) {
            CP_WAIT1();
            __syncthreads();

            if (it + 2 < NIT) load_stage((it + 2) % 3, (it + 2) * BK);
            CP_COMMIT();

            uint32_t stg = sbase + (uint32_t)((it % 3) * STAGE_BYTES);
            #pragma unroll
            for (int kk = 0; kk < BK; kk += 16) {
                uint32_t af[2][4], bq[2][4];
                #pragma unroll
                for (int mi = 0; mi < 2; mi++)
                    ldsm_x4(af[mi][0], af[mi][1], af[mi][2], af[mi][3],
                            stg + aOff[mi] + kk * 2);
                #pragma unroll
                for (int j = 0; j < 2; j++)
                    ldsm_x4_t(bq[j][0], bq[j][1], bq[j][2], bq[j][3],
                              stg + bOff[j] + kk * (LDB * 2));
                #pragma unroll
                for (int mi = 0; mi < 2; mi++)
                    #pragma unroll
                    for (int ni = 0; ni < 4; ni++)
                        mma16816(acc[mi][ni], af[mi], &bq[ni >> 1][(ni & 1) * 2]);
            }
        }

        // ---- epilogue ----
        float alpha = EPI2 ? g_alpha[g] : 0.f;
        const float* bg = bias + (size_t)g * NTOT;
        #pragma unroll
        for (int mi = 0; mi < 2; mi++) {
            #pragma unroll
            for (int half = 0; half < 2; half++) {
                int rloc = wm + mi * 16 + lrow + half * 8;
                int grow = m0 + rloc;
                if (grow >= cnt) continue;
                #pragma unroll
                for (int ni = 0; ni < 4; ni++) {
                    int c = n0 + wn + ni * 8 + lcol;
                    float v0 = acc[mi][ni][half * 2 + 0] + bg[c];
                    float v1 = acc[mi][ni][half * 2 + 1] + bg[c + 1];
                    if (!EPI2) {
                        v0 = fmaxf(v0, 0.f);
                        v1 = fmaxf(v1, 0.f);
                        __nv_bfloat162 pk = __floats2bfloat162_rn(v0, v1);
                        *reinterpret_cast<__nv_bfloat162*>(
                            &g_h[(size_t)(start + grow) * HDIM + c]) = pk;
                    } else {
                        int t = g_perm[start + grow];
                        float2 xv = *reinterpret_cast<const float2*>(x + (size_t)t * DDIM + c);
                        float2 o;
                        o.x = xv.x + alpha * v0;
                        o.y = xv.y + alpha * v1;
                        *reinterpret_cast<float2*>(&g_pre[(size_t)t * DDIM + c]) = o;
                    }
                }
            }
        }
    }
}

// ---------------- normalize: warp-per-row, no block sync ----------------
__global__ void normalize_kernel(float* __restrict__ out) {
    int warp = threadIdx.x >> 5, lane = threadIdx.x & 31;
    int t = blockIdx.x * 8 + warp;
    const float4* pr = reinterpret_cast<const float4*>(g_pre + (size_t)t * DDIM);
    float4 v[6];
    float s = 0.f;
    #pragma unroll
    for (int q = 0; q < 6; q++) {
        v[q] = pr[lane + q * 32];
        s += v[q].x * v[q].x + v[q].y * v[q].y + v[q].z * v[q].z + v[q].w * v[q].w;
    }
    #pragma unroll
    for (int o = 16; o > 0; o >>= 1) s += __shfl_xor_sync(0xffffffffu, s, o);
    float inv = 1.f / fmaxf(sqrtf(s), 1e-12f);
    float4* po = reinterpret_cast<float4*>(out + (size_t)t * DDIM);
    #pragma unroll
    for (int q = 0; q < 6; q++) {
        float4 w = v[q];
        w.x *= inv; w.y *= inv; w.z *= inv; w.w *= inv;
        po[lane + q * 32] = w;
    }
}

// ---------------- launch: prioritized forked-stream graph ----------------
extern "C" void kernel_launch(void* const* d_in, const int* in_sizes, int n_in,
                              void* d_out, int out_size) {
    const float* x         = (const float*)d_in[0];
    const int*   ids       = (const int*)d_in[1];
    const float* W1        = (const float*)d_in[2];
    const float* b1        = (const float*)d_in[3];
    const float* W2        = (const float*)d_in[4];
    const float* b2        = (const float*)d_in[5];
    const float* raw_alpha = (const float*)d_in[6];
    const int*   e2g       = (const int*)d_in[7];
    int T = in_sizes[7];

    static cudaStream_t s1 = nullptr, s2 = nullptr;
    static cudaEvent_t  eRoot = nullptr, eW1a = nullptr, eW1b = nullptr,
                        eW2a = nullptr, eW2b = nullptr;
    static bool smem_set = false;
    if (!s1) {
        cudaStreamCreateWithFlags(&s1, cudaStreamNonBlocking);
        cudaStreamCreateWithFlags(&s2, cudaStreamNonBlocking);
        cudaEventCreateWithFlags(&eRoot, cudaEventDisableTiming);
        cudaEventCreateWithFlags(&eW1a,  cudaEventDisableTiming);
        cudaEventCreateWithFlags(&eW1b,  cudaEventDisableTiming);
        cudaEventCreateWithFlags(&eW2a,  cudaEventDisableTiming);
        cudaEventCreateWithFlags(&eW2b,  cudaEventDisableTiming);
    }
    constexpr int SMEM_GEMM = (64 * 40 + 32 * 136) * 2 * 3;   // 41472 B
    if (!smem_set) {
        cudaFuncSetAttribute(gemm_kernel<DDIM, false>,
                             cudaFuncAttributeMaxDynamicSharedMemorySize, SMEM_GEMM);
        cudaFuncSetAttribute(gemm_kernel<HDIM, true>,
                             cudaFuncAttributeMaxDynamicSharedMemorySize, SMEM_GEMM);
        smem_set = true;
    }

    // fork
    cudaEventRecord(eRoot, 0);
    cudaStreamWaitEvent(s1, eRoot, 0);
    cudaStreamWaitEvent(s2, eRoot, 0);

    // convert W1 FIRST, split across both side streams (full-chip bandwidth);
    // convert W2 follows on the same streams, overlapping gather + GEMM1.
    convert_kernel<<<864, 256, 0, s1>>>(W1, 0, 0);
    convert_kernel<<<864, 256, 0, s2>>>(W1, 0, 864);
    cudaEventRecord(eW1a, s1);
    cudaEventRecord(eW1b, s2);
    convert_kernel<<<864, 256, 0, s1>>>(W2, 1, 0);
    convert_kernel<<<864, 256, 0, s2>>>(W2, 1, 864);
    cudaEventRecord(eW2a, s1);
    cudaEventRecord(eW2b, s2);

    // main branch
    prep_kernel<<<1, 1024>>>(ids, e2g, raw_alpha, T);
    gather_kernel<<<1536, 256>>>(x);

    cudaStreamWaitEvent(0, eW1a, 0);
    cudaStreamWaitEvent(0, eW1b, 0);
    gemm_kernel<DDIM, false><<<NCTA, 256, SMEM_GEMM>>>(b1, x);

    cudaStreamWaitEvent(0, eW2a, 0);
    cudaStreamWaitEvent(0, eW2b, 0);
    gemm_kernel<HDIM, true ><<<NCTA, 256, SMEM_GEMM>>>(b2, x);

    normalize_kernel<<<512, 256>>>((float*)d_out);
}